// round 2
// baseline (speedup 1.0000x reference)
#include <cuda_runtime.h>
#include <math.h>

// Problem constants (fixed shapes per metadata)
#define TT 2048          // tokens (B*S)
#define HH 1024          // hidden
#define EE 8             // experts
#define FF 3584          // ffn intermediate
#define TOPK 2
#define NPAIR (TT * TOPK)

// ---------------- scratch (static device globals; no allocation) ----------------
__device__ int   g_topk_idx[TT][TOPK];
__device__ float g_topk_w[TT][TOPK];
__device__ int   g_counts[EE];
__device__ int   g_offsets[EE];
__device__ int   g_pair_token[NPAIR];
__device__ float g_pair_w[NPAIR];
__device__ float g_act[(size_t)NPAIR * FF];   // ~58.7 MB intermediate activations

// ---------------- zero output ----------------
__global__ void zero_kernel(float* __restrict__ out, int n) {
    int i = blockIdx.x * blockDim.x + threadIdx.x;
    if (i < n) out[i] = 0.0f;
}

// ---------------- router: logits -> top2 -> renormalized weights ----------------
// One warp per token. Softmax+top2+renorm collapses to a 2-way logistic on the
// top-2 logits: w0 = 1/(1+exp(l1-l0)), w1 = 1-w0.
__global__ void router_kernel(const float* __restrict__ x, const float* __restrict__ gw) {
    int warp = (blockIdx.x * blockDim.x + threadIdx.x) >> 5;
    int lane = threadIdx.x & 31;
    if (warp >= TT) return;
    const float* xr = x + (size_t)warp * HH;

    float logit[EE];
#pragma unroll
    for (int e = 0; e < EE; e++) {
        const float* g = gw + (size_t)e * HH;
        float s = 0.0f;
        for (int i = lane; i < HH; i += 32) s += xr[i] * g[i];
#pragma unroll
        for (int o = 16; o > 0; o >>= 1) s += __shfl_xor_sync(0xffffffffu, s, o);
        logit[e] = s;
    }
    if (lane == 0) {
        int i0 = 0;
#pragma unroll
        for (int e = 1; e < EE; e++) if (logit[e] > logit[i0]) i0 = e;
        int i1 = (i0 == 0) ? 1 : 0;
#pragma unroll
        for (int e = 0; e < EE; e++) {
            if (e == i0) continue;
            if (logit[e] > logit[i1]) i1 = e;
        }
        float d = logit[i1] - logit[i0];   // <= 0
        float z = expf(d);
        float w0 = 1.0f / (1.0f + z);
        g_topk_idx[warp][0] = i0;
        g_topk_idx[warp][1] = i1;
        g_topk_w[warp][0] = w0;
        g_topk_w[warp][1] = z * w0;
    }
}

// ---------------- build per-expert compacted pair lists ----------------
__global__ void build_kernel() {
    __shared__ int s_cnt[EE];
    __shared__ int s_cur[EE];
    int tid = threadIdx.x;
    if (tid < EE) s_cnt[tid] = 0;
    __syncthreads();
    for (int p = tid; p < NPAIR; p += blockDim.x)
        atomicAdd(&s_cnt[g_topk_idx[p >> 1][p & 1]], 1);
    __syncthreads();
    if (tid == 0) {
        int off = 0;
        for (int e = 0; e < EE; e++) {
            g_offsets[e] = off;
            g_counts[e]  = s_cnt[e];
            s_cur[e]     = off;
            off += s_cnt[e];
        }
    }
    __syncthreads();
    for (int p = tid; p < NPAIR; p += blockDim.x) {
        int t = p >> 1, k = p & 1;
        int e = g_topk_idx[t][k];
        int slot = atomicAdd(&s_cur[e], 1);
        g_pair_token[slot] = t;
        g_pair_w[slot]     = g_topk_w[t][k];
    }
}

// ---------------- tiled fp32 grouped GEMMs ----------------
#define BM  128
#define BN  64
#define BKC 16

// act[p,f] = silu(x_g @ w1_e^T) * (x_g @ w3_e^T)
__global__ __launch_bounds__(256, 2)
void gemm1_kernel(const float* __restrict__ x,
                  const float* __restrict__ w1,
                  const float* __restrict__ w3) {
    int e    = blockIdx.z;
    int n_e  = g_counts[e];
    int row0 = blockIdx.y * BM;
    if (row0 >= n_e) return;
    int f0   = blockIdx.x * BN;
    int base = g_offsets[e];

    __shared__ float As [BKC][BM];
    __shared__ float Bs1[BKC][BN];
    __shared__ float Bs3[BKC][BN];
    __shared__ int   s_tok[BM];

    int tid = threadIdx.x;
    if (tid < BM) {
        int r = row0 + tid;
        s_tok[tid] = (r < n_e) ? g_pair_token[base + r] : 0;
    }
    __syncthreads();

    int tx = tid & 15;   // 16 groups along N (4 cols each)
    int ty = tid >> 4;   // 16 groups along M (8 rows each)

    float acc1[8][4], acc3[8][4];
#pragma unroll
    for (int i = 0; i < 8; i++)
#pragma unroll
        for (int j = 0; j < 4; j++) { acc1[i][j] = 0.0f; acc3[i][j] = 0.0f; }

    const float* w1b = w1 + ((size_t)e * FF + f0) * HH;
    const float* w3b = w3 + ((size_t)e * FF + f0) * HH;

    int ar0 = (tid      ) >> 2, ac0 = (tid      ) & 3;
    int ar1 = (tid + 256) >> 2, ac1 = (tid + 256) & 3;
    int bf  = tid >> 2,  bc4 = tid & 3;

    for (int k0 = 0; k0 < HH; k0 += BKC) {
        {
            float4 v = *(const float4*)(x + (size_t)s_tok[ar0] * HH + (k0 + ac0 * 4));
            As[ac0*4+0][ar0] = v.x; As[ac0*4+1][ar0] = v.y;
            As[ac0*4+2][ar0] = v.z; As[ac0*4+3][ar0] = v.w;
        }
        {
            float4 v = *(const float4*)(x + (size_t)s_tok[ar1] * HH + (k0 + ac1 * 4));
            As[ac1*4+0][ar1] = v.x; As[ac1*4+1][ar1] = v.y;
            As[ac1*4+2][ar1] = v.z; As[ac1*4+3][ar1] = v.w;
        }
        {
            float4 v1 = *(const float4*)(w1b + (size_t)bf * HH + (k0 + bc4 * 4));
            float4 v3 = *(const float4*)(w3b + (size_t)bf * HH + (k0 + bc4 * 4));
            Bs1[bc4*4+0][bf] = v1.x; Bs1[bc4*4+1][bf] = v1.y;
            Bs1[bc4*4+2][bf] = v1.z; Bs1[bc4*4+3][bf] = v1.w;
            Bs3[bc4*4+0][bf] = v3.x; Bs3[bc4*4+1][bf] = v3.y;
            Bs3[bc4*4+2][bf] = v3.z; Bs3[bc4*4+3][bf] = v3.w;
        }
        __syncthreads();
#pragma unroll
        for (int kk = 0; kk < BKC; kk++) {
            float a[8], b1[4], b3[4];
            *(float4*)&a[0]  = *(const float4*)&As[kk][ty * 8];
            *(float4*)&a[4]  = *(const float4*)&As[kk][ty * 8 + 4];
            *(float4*)&b1[0] = *(const float4*)&Bs1[kk][tx * 4];
            *(float4*)&b3[0] = *(const float4*)&Bs3[kk][tx * 4];
#pragma unroll
            for (int i = 0; i < 8; i++)
#pragma unroll
                for (int j = 0; j < 4; j++) {
                    acc1[i][j] += a[i] * b1[j];
                    acc3[i][j] += a[i] * b3[j];
                }
        }
        __syncthreads();
    }

#pragma unroll
    for (int i = 0; i < 8; i++) {
        int r = row0 + ty * 8 + i;
        if (r >= n_e) continue;
        float4 o;
        float g, u;
        g = acc1[i][0]; u = acc3[i][0]; o.x = (g / (1.0f + expf(-g))) * u;
        g = acc1[i][1]; u = acc3[i][1]; o.y = (g / (1.0f + expf(-g))) * u;
        g = acc1[i][2]; u = acc3[i][2]; o.z = (g / (1.0f + expf(-g))) * u;
        g = acc1[i][3]; u = acc3[i][3]; o.w = (g / (1.0f + expf(-g))) * u;
        *(float4*)(g_act + (size_t)(base + r) * FF + (f0 + tx * 4)) = o;
    }
}

// out[tok,:] += w_pair * (act[p,:] @ w2_e^T)
// Exactly two commutative fp32 atomicAdds land on each out element -> deterministic.
__global__ __launch_bounds__(256, 2)
void gemm2_kernel(const float* __restrict__ w2, float* __restrict__ out) {
    int e    = blockIdx.z;
    int n_e  = g_counts[e];
    int row0 = blockIdx.y * BM;
    if (row0 >= n_e) return;
    int h0   = blockIdx.x * BN;
    int base = g_offsets[e];

    __shared__ float As[BKC][BM];
    __shared__ float Bs[BKC][BN];

    int tid = threadIdx.x;
    int tx = tid & 15;
    int ty = tid >> 4;

    float acc[8][4];
#pragma unroll
    for (int i = 0; i < 8; i++)
#pragma unroll
        for (int j = 0; j < 4; j++) acc[i][j] = 0.0f;

    const float* w2b = w2 + ((size_t)e * HH + h0) * FF;

    int ar0 = (tid      ) >> 2, ac0 = (tid      ) & 3;
    int ar1 = (tid + 256) >> 2, ac1 = (tid + 256) & 3;
    int bh  = tid >> 2,  bc4 = tid & 3;

    int grow0 = base + row0 + ar0; if (grow0 > NPAIR - 1) grow0 = NPAIR - 1;
    int grow1 = base + row0 + ar1; if (grow1 > NPAIR - 1) grow1 = NPAIR - 1;

    for (int k0 = 0; k0 < FF; k0 += BKC) {
        {
            float4 v = *(const float4*)(g_act + (size_t)grow0 * FF + (k0 + ac0 * 4));
            As[ac0*4+0][ar0] = v.x; As[ac0*4+1][ar0] = v.y;
            As[ac0*4+2][ar0] = v.z; As[ac0*4+3][ar0] = v.w;
        }
        {
            float4 v = *(const float4*)(g_act + (size_t)grow1 * FF + (k0 + ac1 * 4));
            As[ac1*4+0][ar1] = v.x; As[ac1*4+1][ar1] = v.y;
            As[ac1*4+2][ar1] = v.z; As[ac1*4+3][ar1] = v.w;
        }
        {
            float4 v = *(const float4*)(w2b + (size_t)bh * FF + (k0 + bc4 * 4));
            Bs[bc4*4+0][bh] = v.x; Bs[bc4*4+1][bh] = v.y;
            Bs[bc4*4+2][bh] = v.z; Bs[bc4*4+3][bh] = v.w;
        }
        __syncthreads();
#pragma unroll
        for (int kk = 0; kk < BKC; kk++) {
            float a[8], b[4];
            *(float4*)&a[0] = *(const float4*)&As[kk][ty * 8];
            *(float4*)&a[4] = *(const float4*)&As[kk][ty * 8 + 4];
            *(float4*)&b[0] = *(const float4*)&Bs[kk][tx * 4];
#pragma unroll
            for (int i = 0; i < 8; i++)
#pragma unroll
                for (int j = 0; j < 4; j++) acc[i][j] += a[i] * b[j];
        }
        __syncthreads();
    }

#pragma unroll
    for (int i = 0; i < 8; i++) {
        int r = row0 + ty * 8 + i;
        if (r >= n_e) continue;
        int prow = base + r;
        int tok  = g_pair_token[prow];
        float wt = g_pair_w[prow];
        float* op = out + (size_t)tok * HH + (h0 + tx * 4);
        atomicAdd(op + 0, acc[i][0] * wt);
        atomicAdd(op + 1, acc[i][1] * wt);
        atomicAdd(op + 2, acc[i][2] * wt);
        atomicAdd(op + 3, acc[i][3] * wt);
    }
}

// ---------------- launch ----------------
extern "C" void kernel_launch(void* const* d_in, const int* in_sizes, int n_in,
                              void* d_out, int out_size) {
    (void)in_sizes; (void)n_in; (void)out_size;
    const float* x  = (const float*)d_in[0];   // hidden_states [1,2048,1024]
    const float* gw = (const float*)d_in[1];   // gate_w [8,1024]
    const float* w1 = (const float*)d_in[2];   // [8,3584,1024]
    const float* w3 = (const float*)d_in[3];   // [8,3584,1024]
    const float* w2 = (const float*)d_in[4];   // [8,1024,3584]
    float* out = (float*)d_out;                // [1,2048,1024]

    zero_kernel<<<(TT * HH + 255) / 256, 256>>>(out, TT * HH);
    router_kernel<<<TT / 8, 256>>>(x, gw);     // 8 warps/block, 1 warp/token
    build_kernel<<<1, 256>>>();

    dim3 g1(FF / BN, TT / BM, EE);             // (56, 16, 8); dead tiles early-exit
    gemm1_kernel<<<g1, 256>>>(x, w1, w3);

    dim3 g2(HH / BN, TT / BM, EE);             // (16, 16, 8)
    gemm2_kernel<<<g2, 256>>>(w2, out);
}

// round 5
// speedup vs baseline: 1.8165x; 1.8165x over previous
#include <cuda_runtime.h>
#include <cuda_bf16.h>
#include <math.h>
#include <stdint.h>

// ---------------- problem constants ----------------
#define TT 2048
#define HH 1024
#define EE 8
#define FF 3584
#define TOPK 2
#define NPAIR (TT * TOPK)
#define BK 32          // K chunk (bf16 elems) per stage
#define ASTR 20        // smem row stride in u32 (= 40 bf16) — conflict-free for frag loads

// ---------------- device scratch (static; no allocation) ----------------
__device__ int      g_topk_idx[TT][TOPK];
__device__ float    g_topk_w[TT][TOPK];
__device__ int      g_counts[EE];
__device__ int      g_offsets[EE];
__device__ int      g_pair_token[NPAIR];
__device__ float    g_pair_w[NPAIR];
__device__ unsigned g_xs[(size_t)TT * HH];      // x split-packed: (hi_bf16 | lo_bf16<<16)
__device__ unsigned g_act[(size_t)NPAIR * FF];  // activations split-packed

// ---------------- helpers ----------------
__device__ __forceinline__ void split1(float v, unsigned short& h, unsigned short& l) {
    __nv_bfloat16 bh = __float2bfloat16_rn(v);
    h = __bfloat16_as_ushort(bh);
    float r = v - __bfloat162float(bh);
    l = __bfloat16_as_ushort(__float2bfloat16_rn(r));
}
__device__ __forceinline__ void split4(float4 v, unsigned& hw0, unsigned& hw1,
                                       unsigned& lw0, unsigned& lw1) {
    unsigned short h0,h1,h2,h3,l0,l1,l2,l3;
    split1(v.x,h0,l0); split1(v.y,h1,l1); split1(v.z,h2,l2); split1(v.w,h3,l3);
    hw0 = (unsigned)h0 | ((unsigned)h1 << 16);
    hw1 = (unsigned)h2 | ((unsigned)h3 << 16);
    lw0 = (unsigned)l0 | ((unsigned)l1 << 16);
    lw1 = (unsigned)l2 | ((unsigned)l3 << 16);
}

// m16n8k16 bf16 mma, f32 accum (base-target PTX, runs on sm_100)
__device__ __forceinline__ void mma16816(float* c, const unsigned* a, unsigned b0, unsigned b1) {
    asm volatile(
        "mma.sync.aligned.m16n8k16.row.col.f32.bf16.bf16.f32 "
        "{%0,%1,%2,%3}, {%4,%5,%6,%7}, {%8,%9}, {%0,%1,%2,%3};"
        : "+f"(c[0]), "+f"(c[1]), "+f"(c[2]), "+f"(c[3])
        : "r"(a[0]), "r"(a[1]), "r"(a[2]), "r"(a[3]), "r"(b0), "r"(b1));
}

// ---------------- small kernels ----------------
__global__ void zero_kernel(float* __restrict__ out, int n) {
    int i = blockIdx.x * blockDim.x + threadIdx.x;
    if (i < n) out[i] = 0.0f;
}

__global__ void split_x_kernel(const float* __restrict__ x) {
    int i = blockIdx.x * blockDim.x + threadIdx.x;
    if (i < TT * HH) {
        unsigned short h, l;
        split1(x[i], h, l);
        g_xs[i] = (unsigned)h | ((unsigned)l << 16);
    }
}

__global__ void router_kernel(const float* __restrict__ x, const float* __restrict__ gw) {
    int warp = (blockIdx.x * blockDim.x + threadIdx.x) >> 5;
    int lane = threadIdx.x & 31;
    if (warp >= TT) return;
    const float* xr = x + (size_t)warp * HH;
    float logit[EE];
#pragma unroll
    for (int e = 0; e < EE; e++) {
        const float* g = gw + (size_t)e * HH;
        float s = 0.0f;
        for (int i = lane; i < HH; i += 32) s += xr[i] * g[i];
#pragma unroll
        for (int o = 16; o > 0; o >>= 1) s += __shfl_xor_sync(0xffffffffu, s, o);
        logit[e] = s;
    }
    if (lane == 0) {
        int i0 = 0;
#pragma unroll
        for (int e = 1; e < EE; e++) if (logit[e] > logit[i0]) i0 = e;
        int i1 = (i0 == 0) ? 1 : 0;
#pragma unroll
        for (int e = 0; e < EE; e++) {
            if (e == i0) continue;
            if (logit[e] > logit[i1]) i1 = e;
        }
        float d = logit[i1] - logit[i0];
        float z = expf(d);
        float w0 = 1.0f / (1.0f + z);
        g_topk_idx[warp][0] = i0;
        g_topk_idx[warp][1] = i1;
        g_topk_w[warp][0] = w0;
        g_topk_w[warp][1] = z * w0;
    }
}

__global__ void build_kernel() {
    __shared__ int s_cnt[EE];
    __shared__ int s_cur[EE];
    int tid = threadIdx.x;
    if (tid < EE) s_cnt[tid] = 0;
    __syncthreads();
    for (int p = tid; p < NPAIR; p += blockDim.x)
        atomicAdd(&s_cnt[g_topk_idx[p >> 1][p & 1]], 1);
    __syncthreads();
    if (tid == 0) {
        int off = 0;
        for (int e = 0; e < EE; e++) {
            g_offsets[e] = off;
            g_counts[e]  = s_cnt[e];
            s_cur[e]     = off;
            off += s_cnt[e];
        }
    }
    __syncthreads();
    for (int p = tid; p < NPAIR; p += blockDim.x) {
        int t = p >> 1, k = p & 1;
        int e = g_topk_idx[t][k];
        int slot = atomicAdd(&s_cur[e], 1);
        g_pair_token[slot] = t;
        g_pair_w[slot]     = g_topk_w[t][k];
    }
}

// ======================= GEMM1: act = silu(x@w1^T) * (x@w3^T) =======================
// CTA: 128 rows x 64 f-cols, computes BOTH g and u. 8 warps: w<4 -> g rows 32w;
// w>=4 -> u rows 32(w-4). K pipelined in BK=32 chunks with register prefetch.
__global__ __launch_bounds__(256, 1)
void gemm1_kernel(const float* __restrict__ w1, const float* __restrict__ w3) {
    __shared__ int      s_tok[128];
    __shared__ unsigned sm[10240];   // 40KB staging; overlaid by epilogue
    unsigned* sAh  = sm;             // 128*20
    unsigned* sAl  = sm + 2560;
    unsigned* sB1h = sm + 5120;      // 64*20 each
    unsigned* sB1l = sm + 6400;
    unsigned* sB3h = sm + 7680;
    unsigned* sB3l = sm + 8960;

    int e    = blockIdx.z;
    int n_e  = g_counts[e];
    int row0 = blockIdx.y * 128;
    if (row0 >= n_e) return;
    int f0   = blockIdx.x * 64;
    int base = g_offsets[e];
    int tid  = threadIdx.x;

    if (tid < 128) {
        int r = row0 + tid;
        s_tok[tid] = (r < n_e) ? g_pair_token[base + r] : 0;
    }
    __syncthreads();

    // staging roles
    int srow = tid >> 1, shalf = tid & 1;                 // A: 2 thr/row, 16 u32 each
    int bmat = tid >> 7, brow = (tid & 127) >> 1, bhalf = tid & 1;  // B: w1|w3, 64 rows
    const unsigned* aptr = g_xs + (size_t)s_tok[srow] * HH + shalf * 16;
    const float*    bptr = (bmat ? w3 : w1) + ((size_t)e * FF + f0 + brow) * HH + bhalf * 16;
    unsigned* sBh = bmat ? sB3h : sB1h;
    unsigned* sBl = bmat ? sB3l : sB1l;
    int aw = srow * ASTR + shalf * 8;
    int bw = brow * ASTR + bhalf * 8;

    // compute roles
    int wid = tid >> 5, lane = tid & 31;
    int isU = wid >> 2;
    int rowblk = (wid & 3) * 32;
    const unsigned* Bh = isU ? sB3h : sB1h;
    const unsigned* Bl = isU ? sB3l : sB1l;
    int r4 = lane >> 2, qk = lane & 3;

    float acc[2][8][4];
#pragma unroll
    for (int mt = 0; mt < 2; mt++)
#pragma unroll
        for (int nt = 0; nt < 8; nt++)
#pragma unroll
            for (int i = 0; i < 4; i++) acc[mt][nt][i] = 0.0f;

    uint4  pa[4];
    float4 pb[4];
    {   // prefetch chunk 0
        const uint4*  as = (const uint4*)(aptr);
        const float4* bs = (const float4*)(bptr);
#pragma unroll
        for (int i = 0; i < 4; i++) { pa[i] = as[i]; pb[i] = bs[i]; }
    }

    const int NC = HH / BK;   // 32
    for (int c = 0; c < NC; c++) {
        // ---- STS (split) ----
#pragma unroll
        for (int i = 0; i < 4; i++) {
            uint4 v = pa[i];
            unsigned h0 = __byte_perm(v.x, v.y, 0x5410), l0 = __byte_perm(v.x, v.y, 0x7632);
            unsigned h1 = __byte_perm(v.z, v.w, 0x5410), l1 = __byte_perm(v.z, v.w, 0x7632);
            *(uint2*)&sAh[aw + i * 2] = make_uint2(h0, h1);
            *(uint2*)&sAl[aw + i * 2] = make_uint2(l0, l1);
        }
#pragma unroll
        for (int i = 0; i < 4; i++) {
            unsigned hw0, hw1, lw0, lw1;
            split4(pb[i], hw0, hw1, lw0, lw1);
            *(uint2*)&sBh[bw + i * 2] = make_uint2(hw0, hw1);
            *(uint2*)&sBl[bw + i * 2] = make_uint2(lw0, lw1);
        }
        __syncthreads();
        if (c + 1 < NC) {   // prefetch next chunk while computing this one
            const uint4*  as = (const uint4*)(aptr + (c + 1) * BK);
            const float4* bs = (const float4*)(bptr + (c + 1) * BK);
#pragma unroll
            for (int i = 0; i < 4; i++) { pa[i] = as[i]; pb[i] = bs[i]; }
        }
        // ---- mma: 2 k16 steps x 3 split terms ----
#pragma unroll
        for (int ks = 0; ks < 2; ks++) {
            int kw = ks * 8 + qk;
            unsigned ah[2][4], al[2][4];
#pragma unroll
            for (int mt = 0; mt < 2; mt++) {
                int rb = (rowblk + mt * 16 + r4) * ASTR;
                ah[mt][0] = sAh[rb + kw];            ah[mt][1] = sAh[rb + 8 * ASTR + kw];
                ah[mt][2] = sAh[rb + kw + 4];        ah[mt][3] = sAh[rb + 8 * ASTR + kw + 4];
                al[mt][0] = sAl[rb + kw];            al[mt][1] = sAl[rb + 8 * ASTR + kw];
                al[mt][2] = sAl[rb + kw + 4];        al[mt][3] = sAl[rb + 8 * ASTR + kw + 4];
            }
#pragma unroll
            for (int nt = 0; nt < 8; nt++) {
                int nb = (nt * 8 + r4) * ASTR;
                unsigned bh0 = Bh[nb + kw], bh1 = Bh[nb + kw + 4];
                unsigned bl0 = Bl[nb + kw], bl1 = Bl[nb + kw + 4];
#pragma unroll
                for (int mt = 0; mt < 2; mt++) {
                    mma16816(acc[mt][nt], ah[mt], bh0, bh1);
                    mma16816(acc[mt][nt], ah[mt], bl0, bl1);
                    mma16816(acc[mt][nt], al[mt], bh0, bh1);
                }
            }
        }
        __syncthreads();
    }

    // ---- epilogue: u-warps publish u; g-warps combine; coalesced store ----
    float*    epf = (float*)sm;       // 128 x 64, stride 66
    unsigned* epu = sm;
    if (isU) {
#pragma unroll
        for (int mt = 0; mt < 2; mt++)
#pragma unroll
            for (int nt = 0; nt < 8; nt++)
#pragma unroll
                for (int i = 0; i < 4; i++) {
                    int row = rowblk + mt * 16 + r4 + ((i >> 1) ? 8 : 0);
                    int col = nt * 8 + qk * 2 + (i & 1);
                    epf[row * 66 + col] = acc[mt][nt][i];
                }
    }
    __syncthreads();
    if (!isU) {
#pragma unroll
        for (int mt = 0; mt < 2; mt++)
#pragma unroll
            for (int nt = 0; nt < 8; nt++)
#pragma unroll
                for (int i = 0; i < 4; i++) {
                    int row = rowblk + mt * 16 + r4 + ((i >> 1) ? 8 : 0);
                    int col = nt * 8 + qk * 2 + (i & 1);
                    float u = epf[row * 66 + col];
                    float g = acc[mt][nt][i];
                    float y = (g / (1.0f + expf(-g))) * u;
                    unsigned short h, l;
                    split1(y, h, l);
                    epu[row * 66 + col] = (unsigned)h | ((unsigned)l << 16);
                }
    }
    __syncthreads();
    for (int idx = tid; idx < 128 * 64; idx += 256) {
        int rr = idx >> 6, cc = idx & 63;
        if (row0 + rr < n_e)
            g_act[(size_t)(base + row0 + rr) * FF + f0 + cc] = epu[rr * 66 + cc];
    }
}

// ======================= GEMM2: out += wt * (act @ w2^T) =======================
// CTA: 128 rows x 128 h-cols. 8 warps in 4x2: warp tile 32x64.
__global__ __launch_bounds__(256, 1)
void gemm2_kernel(const float* __restrict__ w2, float* __restrict__ out) {
    __shared__ int      s_tok[128];
    __shared__ float    s_wt[128];
    __shared__ unsigned sm[10240];
    unsigned* sAh = sm;              // 128*20
    unsigned* sAl = sm + 2560;
    unsigned* sBh = sm + 5120;       // 128*20
    unsigned* sBl = sm + 7680;

    int e    = blockIdx.z;
    int n_e  = g_counts[e];
    int row0 = blockIdx.y * 128;
    if (row0 >= n_e) return;
    int h0   = blockIdx.x * 128;
    int base = g_offsets[e];
    int tid  = threadIdx.x;

    if (tid < 128) {
        int r = row0 + tid;
        s_tok[tid] = (r < n_e) ? g_pair_token[base + r] : 0;
        s_wt[tid]  = (r < n_e) ? g_pair_w[base + r] : 0.0f;
    }
    __syncthreads();

    // staging roles
    int srow = tid >> 1, shalf = tid & 1;
    long arow = (long)base + row0 + srow;
    if (arow > NPAIR - 1) arow = NPAIR - 1;
    const unsigned* aptr = g_act + (size_t)arow * FF + shalf * 16;
    const float*    bptr = w2 + ((size_t)e * HH + h0 + srow) * FF + shalf * 16;
    int aw = srow * ASTR + shalf * 8;

    // compute roles
    int wid = tid >> 5, lane = tid & 31;
    int rowblk = (wid & 3) * 32;
    int colblk = (wid >> 2) * 64;
    int r4 = lane >> 2, qk = lane & 3;

    float acc[2][8][4];
#pragma unroll
    for (int mt = 0; mt < 2; mt++)
#pragma unroll
        for (int nt = 0; nt < 8; nt++)
#pragma unroll
            for (int i = 0; i < 4; i++) acc[mt][nt][i] = 0.0f;

    uint4  pa[4];
    float4 pb[4];
    {
        const uint4*  as = (const uint4*)(aptr);
        const float4* bs = (const float4*)(bptr);
#pragma unroll
        for (int i = 0; i < 4; i++) { pa[i] = as[i]; pb[i] = bs[i]; }
    }

    const int NC = FF / BK;   // 112
    for (int c = 0; c < NC; c++) {
#pragma unroll
        for (int i = 0; i < 4; i++) {
            uint4 v = pa[i];
            unsigned h0w = __byte_perm(v.x, v.y, 0x5410), l0w = __byte_perm(v.x, v.y, 0x7632);
            unsigned h1w = __byte_perm(v.z, v.w, 0x5410), l1w = __byte_perm(v.z, v.w, 0x7632);
            *(uint2*)&sAh[aw + i * 2] = make_uint2(h0w, h1w);
            *(uint2*)&sAl[aw + i * 2] = make_uint2(l0w, l1w);
        }
#pragma unroll
        for (int i = 0; i < 4; i++) {
            unsigned hw0, hw1, lw0, lw1;
            split4(pb[i], hw0, hw1, lw0, lw1);
            *(uint2*)&sBh[aw + i * 2] = make_uint2(hw0, hw1);
            *(uint2*)&sBl[aw + i * 2] = make_uint2(lw0, lw1);
        }
        __syncthreads();
        if (c + 1 < NC) {
            const uint4*  as = (const uint4*)(aptr + (c + 1) * BK);
            const float4* bs = (const float4*)(bptr + (c + 1) * BK);
#pragma unroll
            for (int i = 0; i < 4; i++) { pa[i] = as[i]; pb[i] = bs[i]; }
        }
#pragma unroll
        for (int ks = 0; ks < 2; ks++) {
            int kw = ks * 8 + qk;
            unsigned ah[2][4], al[2][4];
#pragma unroll
            for (int mt = 0; mt < 2; mt++) {
                int rb = (rowblk + mt * 16 + r4) * ASTR;
                ah[mt][0] = sAh[rb + kw];            ah[mt][1] = sAh[rb + 8 * ASTR + kw];
                ah[mt][2] = sAh[rb + kw + 4];        ah[mt][3] = sAh[rb + 8 * ASTR + kw + 4];
                al[mt][0] = sAl[rb + kw];            al[mt][1] = sAl[rb + 8 * ASTR + kw];
                al[mt][2] = sAl[rb + kw + 4];        al[mt][3] = sAl[rb + 8 * ASTR + kw + 4];
            }
#pragma unroll
            for (int nt = 0; nt < 8; nt++) {
                int nb = (colblk + nt * 8 + r4) * ASTR;
                unsigned bh0 = sBh[nb + kw], bh1 = sBh[nb + kw + 4];
                unsigned bl0 = sBl[nb + kw], bl1 = sBl[nb + kw + 4];
#pragma unroll
                for (int mt = 0; mt < 2; mt++) {
                    mma16816(acc[mt][nt], ah[mt], bh0, bh1);
                    mma16816(acc[mt][nt], ah[mt], bl0, bl1);
                    mma16816(acc[mt][nt], al[mt], bh0, bh1);
                }
            }
        }
        __syncthreads();
    }

    // ---- epilogue: weighted atomic combine (exactly 2 adds per out element) ----
#pragma unroll
    for (int mt = 0; mt < 2; mt++)
#pragma unroll
        for (int i2 = 0; i2 < 2; i2++) {           // i2: 0 -> regs {0,1}, 1 -> regs {2,3}
            int row = rowblk + mt * 16 + r4 + i2 * 8;
            if (row0 + row >= n_e) continue;
            float wt = s_wt[row];
            float* op = out + (size_t)s_tok[row] * HH + h0;
#pragma unroll
            for (int nt = 0; nt < 8; nt++) {
                int col = colblk + nt * 8 + qk * 2;
                atomicAdd(op + col,     acc[mt][nt][i2 * 2]     * wt);
                atomicAdd(op + col + 1, acc[mt][nt][i2 * 2 + 1] * wt);
            }
        }
}

// ---------------- launch ----------------
extern "C" void kernel_launch(void* const* d_in, const int* in_sizes, int n_in,
                              void* d_out, int out_size) {
    (void)in_sizes; (void)n_in; (void)out_size;
    const float* x  = (const float*)d_in[0];
    const float* gw = (const float*)d_in[1];
    const float* w1 = (const float*)d_in[2];
    const float* w3 = (const float*)d_in[3];
    const float* w2 = (const float*)d_in[4];
    float* out = (float*)d_out;

    zero_kernel<<<(TT * HH + 255) / 256, 256>>>(out, TT * HH);
    split_x_kernel<<<(TT * HH + 255) / 256, 256>>>(x);
    router_kernel<<<TT / 8, 256>>>(x, gw);
    build_kernel<<<1, 256>>>();

    dim3 g1(FF / 64, TT / 128, EE);    // (56,16,8); dead tiles early-exit
    gemm1_kernel<<<g1, 256>>>(w1, w3);

    dim3 g2(HH / 128, TT / 128, EE);   // (8,16,8)
    gemm2_kernel<<<g2, 256>>>(w2, out);
}

// round 6
// speedup vs baseline: 2.1551x; 1.1864x over previous
#include <cuda_runtime.h>
#include <cuda_bf16.h>
#include <math.h>
#include <stdint.h>

// ---------------- problem constants ----------------
#define TT 2048
#define HH 1024
#define EE 8
#define FF 3584
#define TOPK 2
#define NPAIR (TT * TOPK)
#define BK 32              // K elems per chunk (=128B per row)
#define NS 3               // pipeline stages
#define ROWB 160           // smem row stride bytes (40 u32: 32 data + 8 pad, 16B aligned)
#define ASTG 20480         // 128 rows * 160B  (A tile)
#define STG  40960         // A + B per stage
#define SMEM_DYN (NS * STG)   // 122880 B dynamic smem

// ---------------- device scratch (static; no allocation) ----------------
__device__ int      g_topk_idx[TT][TOPK];
__device__ float    g_topk_w[TT][TOPK];
__device__ int      g_counts[EE];
__device__ int      g_offsets[EE];
__device__ int      g_pair_token[NPAIR];
__device__ float    g_pair_w[NPAIR];
__device__ unsigned g_xs[(size_t)TT * HH];      // x split-packed (hi | lo<<16)
__device__ unsigned g_act[(size_t)NPAIR * FF];  // activations split-packed

// ---------------- helpers ----------------
__device__ __forceinline__ uint32_t smem_u32(const void* p) {
    uint32_t a;
    asm("{ .reg .u64 t; cvta.to.shared.u64 t, %1; cvt.u32.u64 %0, t; }" : "=r"(a) : "l"(p));
    return a;
}
#define CP16(dst_u32, src_ptr) \
    asm volatile("cp.async.cg.shared.global [%0], [%1], 16;" :: "r"(dst_u32), "l"(src_ptr) : "memory")
#define CP_COMMIT() asm volatile("cp.async.commit_group;" ::: "memory")
#define CP_WAIT(n)  asm volatile("cp.async.wait_group %0;" :: "n"(n) : "memory")

__device__ __forceinline__ void split1(float v, unsigned short& h, unsigned short& l) {
    __nv_bfloat16 bh = __float2bfloat16_rn(v);
    h = __bfloat16_as_ushort(bh);
    float r = v - __bfloat162float(bh);
    l = __bfloat16_as_ushort(__float2bfloat16_rn(r));
}
// pack: low 16 = bf16(lo_val), high 16 = bf16(hi_val)
__device__ __forceinline__ unsigned cvt_bf2(float lo_val, float hi_val) {
    unsigned r;
    asm("cvt.rn.bf16x2.f32 %0, %1, %2;" : "=r"(r) : "f"(hi_val), "f"(lo_val));
    return r;
}
// fp32 pair (k even, k odd) -> (hi packed, lo packed) bf16x2 regs
__device__ __forceinline__ void split2(float2 f, unsigned& h, unsigned& l) {
    h = cvt_bf2(f.x, f.y);
    float hx = __uint_as_float(h << 16);
    float hy = __uint_as_float(h & 0xffff0000u);
    l = cvt_bf2(f.x - hx, f.y - hy);
}
__device__ __forceinline__ void mma16816(float* c, const unsigned* a, unsigned b0, unsigned b1) {
    asm volatile(
        "mma.sync.aligned.m16n8k16.row.col.f32.bf16.bf16.f32 "
        "{%0,%1,%2,%3}, {%4,%5,%6,%7}, {%8,%9}, {%0,%1,%2,%3};"
        : "+f"(c[0]), "+f"(c[1]), "+f"(c[2]), "+f"(c[3])
        : "r"(a[0]), "r"(a[1]), "r"(a[2]), "r"(a[3]), "r"(b0), "r"(b1));
}

// ---------------- small kernels ----------------
__global__ void zero_kernel(float* __restrict__ out, int n) {
    int i = blockIdx.x * blockDim.x + threadIdx.x;
    if (i < n) out[i] = 0.0f;
}
__global__ void split_x_kernel(const float* __restrict__ x) {
    int i = blockIdx.x * blockDim.x + threadIdx.x;
    if (i < TT * HH) {
        unsigned short h, l;
        split1(x[i], h, l);
        g_xs[i] = (unsigned)h | ((unsigned)l << 16);
    }
}
__global__ void router_kernel(const float* __restrict__ x, const float* __restrict__ gw) {
    int warp = (blockIdx.x * blockDim.x + threadIdx.x) >> 5;
    int lane = threadIdx.x & 31;
    if (warp >= TT) return;
    const float* xr = x + (size_t)warp * HH;
    float logit[EE];
#pragma unroll
    for (int e = 0; e < EE; e++) {
        const float* g = gw + (size_t)e * HH;
        float s = 0.0f;
        for (int i = lane; i < HH; i += 32) s += xr[i] * g[i];
#pragma unroll
        for (int o = 16; o > 0; o >>= 1) s += __shfl_xor_sync(0xffffffffu, s, o);
        logit[e] = s;
    }
    if (lane == 0) {
        int i0 = 0;
#pragma unroll
        for (int e = 1; e < EE; e++) if (logit[e] > logit[i0]) i0 = e;
        int i1 = (i0 == 0) ? 1 : 0;
#pragma unroll
        for (int e = 0; e < EE; e++) {
            if (e == i0) continue;
            if (logit[e] > logit[i1]) i1 = e;
        }
        float d = logit[i1] - logit[i0];
        float z = expf(d);
        float w0 = 1.0f / (1.0f + z);
        g_topk_idx[warp][0] = i0;
        g_topk_idx[warp][1] = i1;
        g_topk_w[warp][0] = w0;
        g_topk_w[warp][1] = z * w0;
    }
}
__global__ void build_kernel() {
    __shared__ int s_cnt[EE];
    __shared__ int s_cur[EE];
    int tid = threadIdx.x;
    if (tid < EE) s_cnt[tid] = 0;
    __syncthreads();
    for (int p = tid; p < NPAIR; p += blockDim.x)
        atomicAdd(&s_cnt[g_topk_idx[p >> 1][p & 1]], 1);
    __syncthreads();
    if (tid == 0) {
        int off = 0;
        for (int e = 0; e < EE; e++) {
            g_offsets[e] = off;
            g_counts[e]  = s_cnt[e];
            s_cur[e]     = off;
            off += s_cnt[e];
        }
    }
    __syncthreads();
    for (int p = tid; p < NPAIR; p += blockDim.x) {
        int t = p >> 1, k = p & 1;
        int e = g_topk_idx[t][k];
        int slot = atomicAdd(&s_cur[e], 1);
        g_pair_token[slot] = t;
        g_pair_w[slot]     = g_topk_w[t][k];
    }
}

// ======================= GEMM1: act = silu(x@w1^T) * (x@w3^T) =======================
// CTA 128 rows x 64 f-cols; warps 0-3 compute g (w1), warps 4-7 compute u (w3).
// 3-stage cp.async pipeline; A packed (hi|lo), B fp32 split at frag-load.
__global__ __launch_bounds__(256)
void gemm1_kernel(const float* __restrict__ w1, const float* __restrict__ w3) {
    extern __shared__ char dsm[];
    __shared__ int s_tok[128];

    int e    = blockIdx.z;
    int n_e  = g_counts[e];
    int row0 = blockIdx.y * 128;
    if (row0 >= n_e) return;
    int f0   = blockIdx.x * 64;
    int base = g_offsets[e];
    int tid  = threadIdx.x;

    if (tid < 128) {
        int r = row0 + tid;
        s_tok[tid] = (r < n_e) ? g_pair_token[base + r] : 0;
    }
    __syncthreads();

    // per-thread cp.async descriptors (4 A-chunks + 4 B-chunks of 16B per k-chunk)
    const char* srcA[4];
    const char* srcB[4];
    int dofA[4], dofB[4];
#pragma unroll
    for (int i = 0; i < 4; i++) {
        int idx = tid + 256 * i;
        int row = idx >> 3, c = idx & 7;
        srcA[i] = (const char*)(g_xs + (size_t)s_tok[row] * HH) + c * 16;
        const float* wb = (row < 64)
            ? w1 + ((size_t)e * FF + f0 + row) * HH
            : w3 + ((size_t)e * FF + f0 + row - 64) * HH;
        srcB[i] = (const char*)wb + c * 16;
        dofA[i] = row * ROWB + c * 16;
        dofB[i] = ASTG + row * ROWB + c * 16;
    }
    uint32_t sb0 = smem_u32(dsm);

    auto issue = [&](int s) {
        uint32_t sg = sb0 + s * STG;
#pragma unroll
        for (int i = 0; i < 4; i++) { CP16(sg + dofA[i], srcA[i]); srcA[i] += 128; }
#pragma unroll
        for (int i = 0; i < 4; i++) { CP16(sg + dofB[i], srcB[i]); srcB[i] += 128; }
        CP_COMMIT();
    };
    issue(0);
    issue(1);

    // compute roles
    int wid = tid >> 5, lane = tid & 31;
    int isU = wid >> 2;
    int rowblk = (wid & 3) * 32;
    int r4 = lane >> 2, qk = lane & 3;
    int aoff = (rowblk + r4) * ROWB + qk * 8;          // A frag byte base
    int boff = ASTG + (isU * 64 + r4) * ROWB + qk * 8; // B frag byte base

    float acc[2][8][4];
#pragma unroll
    for (int mt = 0; mt < 2; mt++)
#pragma unroll
        for (int nt = 0; nt < 8; nt++)
#pragma unroll
            for (int i = 0; i < 4; i++) acc[mt][nt][i] = 0.0f;

    const int NC = HH / BK;   // 32
    for (int c = 0; c < NC; c++) {
        if (c < NC - 1) { CP_WAIT(1); } else { CP_WAIT(0); }
        __syncthreads();
        if (c + 2 < NC) issue((c + 2) % NS);

        const char* stg = dsm + (c % NS) * STG;
#pragma unroll
        for (int ks = 0; ks < 2; ks++) {
            unsigned ah[2][4], al[2][4];
#pragma unroll
            for (int mt = 0; mt < 2; mt++) {
                const char* p = stg + aoff + mt * 16 * ROWB + ks * 64;
                uint2 u0 = *(const uint2*)(p);
                uint2 u1 = *(const uint2*)(p + 8 * ROWB);
                uint2 u2 = *(const uint2*)(p + 32);
                uint2 u3 = *(const uint2*)(p + 8 * ROWB + 32);
                ah[mt][0] = __byte_perm(u0.x, u0.y, 0x5410); al[mt][0] = __byte_perm(u0.x, u0.y, 0x7632);
                ah[mt][1] = __byte_perm(u1.x, u1.y, 0x5410); al[mt][1] = __byte_perm(u1.x, u1.y, 0x7632);
                ah[mt][2] = __byte_perm(u2.x, u2.y, 0x5410); al[mt][2] = __byte_perm(u2.x, u2.y, 0x7632);
                ah[mt][3] = __byte_perm(u3.x, u3.y, 0x5410); al[mt][3] = __byte_perm(u3.x, u3.y, 0x7632);
            }
#pragma unroll
            for (int nt = 0; nt < 8; nt++) {
                const char* q = stg + boff + nt * 8 * ROWB + ks * 64;
                float2 f01 = *(const float2*)(q);
                float2 f23 = *(const float2*)(q + 32);
                unsigned bh0, bl0, bh1, bl1;
                split2(f01, bh0, bl0);
                split2(f23, bh1, bl1);
                mma16816(acc[0][nt], ah[0], bh0, bh1);
                mma16816(acc[1][nt], ah[1], bh0, bh1);
                mma16816(acc[0][nt], ah[0], bl0, bl1);
                mma16816(acc[1][nt], ah[1], bl0, bl1);
                mma16816(acc[0][nt], al[0], bh0, bh1);
                mma16816(acc[1][nt], al[1], bh0, bh1);
            }
        }
    }
    __syncthreads();   // all mma reads done before smem reuse

    // ---- epilogue: u-warps publish u via smem; g-warps combine; coalesced store ----
    float*    epf = (float*)dsm;       // 128 x 64, stride 66
    unsigned* epu = (unsigned*)dsm;
    if (isU) {
#pragma unroll
        for (int mt = 0; mt < 2; mt++)
#pragma unroll
            for (int nt = 0; nt < 8; nt++)
#pragma unroll
                for (int i = 0; i < 4; i++) {
                    int row = rowblk + mt * 16 + r4 + ((i >> 1) ? 8 : 0);
                    int col = nt * 8 + qk * 2 + (i & 1);
                    epf[row * 66 + col] = acc[mt][nt][i];
                }
    }
    __syncthreads();
    if (!isU) {
#pragma unroll
        for (int mt = 0; mt < 2; mt++)
#pragma unroll
            for (int nt = 0; nt < 8; nt++)
#pragma unroll
                for (int i = 0; i < 4; i++) {
                    int row = rowblk + mt * 16 + r4 + ((i >> 1) ? 8 : 0);
                    int col = nt * 8 + qk * 2 + (i & 1);
                    float u = epf[row * 66 + col];
                    float g = acc[mt][nt][i];
                    float y = (g / (1.0f + expf(-g))) * u;
                    unsigned short h, l;
                    split1(y, h, l);
                    epu[row * 66 + col] = (unsigned)h | ((unsigned)l << 16);
                }
    }
    __syncthreads();
    for (int idx = tid; idx < 128 * 64; idx += 256) {
        int rr = idx >> 6, cc = idx & 63;
        if (row0 + rr < n_e)
            g_act[(size_t)(base + row0 + rr) * FF + f0 + cc] = epu[rr * 66 + cc];
    }
}

// ======================= GEMM2: out += wt * (act @ w2^T) =======================
// CTA 128 rows x 128 h-cols; warps 4x2 (32x64 per warp). Same pipeline.
__global__ __launch_bounds__(256)
void gemm2_kernel(const float* __restrict__ w2, float* __restrict__ out) {
    extern __shared__ char dsm[];
    __shared__ int   s_tok[128];
    __shared__ float s_wt[128];

    int e    = blockIdx.z;
    int n_e  = g_counts[e];
    int row0 = blockIdx.y * 128;
    if (row0 >= n_e) return;
    int h0   = blockIdx.x * 128;
    int base = g_offsets[e];
    int tid  = threadIdx.x;

    if (tid < 128) {
        int r = row0 + tid;
        s_tok[tid] = (r < n_e) ? g_pair_token[base + r] : 0;
        s_wt[tid]  = (r < n_e) ? g_pair_w[base + r] : 0.0f;
    }
    __syncthreads();

    const char* srcA[4];
    const char* srcB[4];
    int dofA[4], dofB[4];
#pragma unroll
    for (int i = 0; i < 4; i++) {
        int idx = tid + 256 * i;
        int row = idx >> 3, c = idx & 7;
        long arow = (long)base + row0 + row;
        if (arow > NPAIR - 1) arow = NPAIR - 1;
        srcA[i] = (const char*)(g_act + (size_t)arow * FF) + c * 16;
        srcB[i] = (const char*)(w2 + ((size_t)e * HH + h0 + row) * FF) + c * 16;
        dofA[i] = row * ROWB + c * 16;
        dofB[i] = ASTG + row * ROWB + c * 16;
    }
    uint32_t sb0 = smem_u32(dsm);
    auto issue = [&](int s) {
        uint32_t sg = sb0 + s * STG;
#pragma unroll
        for (int i = 0; i < 4; i++) { CP16(sg + dofA[i], srcA[i]); srcA[i] += 128; }
#pragma unroll
        for (int i = 0; i < 4; i++) { CP16(sg + dofB[i], srcB[i]); srcB[i] += 128; }
        CP_COMMIT();
    };
    issue(0);
    issue(1);

    int wid = tid >> 5, lane = tid & 31;
    int rowblk = (wid & 3) * 32;
    int colblk = (wid >> 2) * 64;
    int r4 = lane >> 2, qk = lane & 3;
    int aoff = (rowblk + r4) * ROWB + qk * 8;
    int boff = ASTG + (colblk + r4) * ROWB + qk * 8;

    float acc[2][8][4];
#pragma unroll
    for (int mt = 0; mt < 2; mt++)
#pragma unroll
        for (int nt = 0; nt < 8; nt++)
#pragma unroll
            for (int i = 0; i < 4; i++) acc[mt][nt][i] = 0.0f;

    const int NC = FF / BK;   // 112
    for (int c = 0; c < NC; c++) {
        if (c < NC - 1) { CP_WAIT(1); } else { CP_WAIT(0); }
        __syncthreads();
        if (c + 2 < NC) issue((c + 2) % NS);

        const char* stg = dsm + (c % NS) * STG;
#pragma unroll
        for (int ks = 0; ks < 2; ks++) {
            unsigned ah[2][4], al[2][4];
#pragma unroll
            for (int mt = 0; mt < 2; mt++) {
                const char* p = stg + aoff + mt * 16 * ROWB + ks * 64;
                uint2 u0 = *(const uint2*)(p);
                uint2 u1 = *(const uint2*)(p + 8 * ROWB);
                uint2 u2 = *(const uint2*)(p + 32);
                uint2 u3 = *(const uint2*)(p + 8 * ROWB + 32);
                ah[mt][0] = __byte_perm(u0.x, u0.y, 0x5410); al[mt][0] = __byte_perm(u0.x, u0.y, 0x7632);
                ah[mt][1] = __byte_perm(u1.x, u1.y, 0x5410); al[mt][1] = __byte_perm(u1.x, u1.y, 0x7632);
                ah[mt][2] = __byte_perm(u2.x, u2.y, 0x5410); al[mt][2] = __byte_perm(u2.x, u2.y, 0x7632);
                ah[mt][3] = __byte_perm(u3.x, u3.y, 0x5410); al[mt][3] = __byte_perm(u3.x, u3.y, 0x7632);
            }
#pragma unroll
            for (int nt = 0; nt < 8; nt++) {
                const char* q = stg + boff + nt * 8 * ROWB + ks * 64;
                float2 f01 = *(const float2*)(q);
                float2 f23 = *(const float2*)(q + 32);
                unsigned bh0, bl0, bh1, bl1;
                split2(f01, bh0, bl0);
                split2(f23, bh1, bl1);
                mma16816(acc[0][nt], ah[0], bh0, bh1);
                mma16816(acc[1][nt], ah[1], bh0, bh1);
                mma16816(acc[0][nt], ah[0], bl0, bl1);
                mma16816(acc[1][nt], ah[1], bl0, bl1);
                mma16816(acc[0][nt], al[0], bh0, bh1);
                mma16816(acc[1][nt], al[1], bh0, bh1);
            }
        }
    }

    // ---- epilogue: weighted atomic combine (exactly 2 adds per out element) ----
#pragma unroll
    for (int mt = 0; mt < 2; mt++)
#pragma unroll
        for (int i2 = 0; i2 < 2; i2++) {
            int row = rowblk + mt * 16 + r4 + i2 * 8;
            if (row0 + row >= n_e) continue;
            float wt = s_wt[row];
            float* op = out + (size_t)s_tok[row] * HH + h0;
#pragma unroll
            for (int nt = 0; nt < 8; nt++) {
                int col = colblk + nt * 8 + qk * 2;
                atomicAdd(op + col,     acc[mt][nt][i2 * 2]     * wt);
                atomicAdd(op + col + 1, acc[mt][nt][i2 * 2 + 1] * wt);
            }
        }
}

// ---------------- launch ----------------
extern "C" void kernel_launch(void* const* d_in, const int* in_sizes, int n_in,
                              void* d_out, int out_size) {
    (void)in_sizes; (void)n_in; (void)out_size;
    const float* x  = (const float*)d_in[0];
    const float* gw = (const float*)d_in[1];
    const float* w1 = (const float*)d_in[2];
    const float* w3 = (const float*)d_in[3];
    const float* w2 = (const float*)d_in[4];
    float* out = (float*)d_out;

    cudaFuncSetAttribute(gemm1_kernel, cudaFuncAttributeMaxDynamicSharedMemorySize, SMEM_DYN);
    cudaFuncSetAttribute(gemm2_kernel, cudaFuncAttributeMaxDynamicSharedMemorySize, SMEM_DYN);

    zero_kernel<<<(TT * HH + 255) / 256, 256>>>(out, TT * HH);
    split_x_kernel<<<(TT * HH + 255) / 256, 256>>>(x);
    router_kernel<<<TT / 8, 256>>>(x, gw);
    build_kernel<<<1, 256>>>();

    dim3 g1(FF / 64, TT / 128, EE);    // (56,16,8); dead tiles early-exit
    gemm1_kernel<<<g1, 256, SMEM_DYN>>>(w1, w3);

    dim3 g2(HH / 128, TT / 128, EE);   // (8,16,8)
    gemm2_kernel<<<g2, 256, SMEM_DYN>>>(w2, out);
}

// round 7
// speedup vs baseline: 2.4858x; 1.1534x over previous
#include <cuda_runtime.h>
#include <math.h>
#include <stdint.h>

// ---------------- problem constants ----------------
#define TT 2048
#define HH 1024
#define EE 8
#define FF 3584
#define TOPK 2
#define NPAIR (TT * TOPK)
#define BK 32               // K floats per chunk (=128B per row)
#define NS 3                // pipeline stages
#define ROWB 144            // smem row stride bytes (36 floats: 32 data + 4 pad)
#define ROWF 36
#define ASTG (128 * ROWB)   // 18432 B (A tile: 128 rows)
#define STG  (2 * ASTG)     // 36864 B (A + B per stage)
#define SMEM_DYN (NS * STG) // 110592 B

// ---------------- device scratch (static; no allocation) ----------------
__device__ int   g_topk_idx[TT][TOPK];
__device__ float g_topk_w[TT][TOPK];
__device__ int   g_counts[EE];
__device__ int   g_offsets[EE];
__device__ int   g_pair_token[NPAIR];
__device__ float g_pair_w[NPAIR];
__device__ float g_act[(size_t)NPAIR * FF];   // fp32 intermediate activations

// ---------------- helpers ----------------
__device__ __forceinline__ uint32_t smem_u32(const void* p) {
    uint32_t a;
    asm("{ .reg .u64 t; cvta.to.shared.u64 t, %1; cvt.u32.u64 %0, t; }" : "=r"(a) : "l"(p));
    return a;
}
#define CP16(dst_u32, src_ptr) \
    asm volatile("cp.async.cg.shared.global [%0], [%1], 16;" :: "r"(dst_u32), "l"(src_ptr) : "memory")
#define CP_COMMIT() asm volatile("cp.async.commit_group;" ::: "memory")
#define CP_WAIT(n)  asm volatile("cp.async.wait_group %0;" :: "n"(n) : "memory")

__device__ __forceinline__ unsigned tf32r(float v) {
    unsigned r;
    asm("cvt.rna.tf32.f32 %0, %1;" : "=r"(r) : "f"(v));
    return r;
}
// m16n8k8 tf32 mma, f32 accum
__device__ __forceinline__ void mma1688(float* c, const unsigned* a, unsigned b0, unsigned b1) {
    asm volatile(
        "mma.sync.aligned.m16n8k8.row.col.f32.tf32.tf32.f32 "
        "{%0,%1,%2,%3}, {%4,%5,%6,%7}, {%8,%9}, {%0,%1,%2,%3};"
        : "+f"(c[0]), "+f"(c[1]), "+f"(c[2]), "+f"(c[3])
        : "r"(a[0]), "r"(a[1]), "r"(a[2]), "r"(a[3]), "r"(b0), "r"(b1));
}

// ---------------- small kernels ----------------
__global__ void zero_kernel(float* __restrict__ out, int n) {
    int i = blockIdx.x * blockDim.x + threadIdx.x;
    if (i < n) out[i] = 0.0f;
}
__global__ void router_kernel(const float* __restrict__ x, const float* __restrict__ gw) {
    int warp = (blockIdx.x * blockDim.x + threadIdx.x) >> 5;
    int lane = threadIdx.x & 31;
    if (warp >= TT) return;
    const float* xr = x + (size_t)warp * HH;
    float logit[EE];
#pragma unroll
    for (int e = 0; e < EE; e++) {
        const float* g = gw + (size_t)e * HH;
        float s = 0.0f;
        for (int i = lane; i < HH; i += 32) s += xr[i] * g[i];
#pragma unroll
        for (int o = 16; o > 0; o >>= 1) s += __shfl_xor_sync(0xffffffffu, s, o);
        logit[e] = s;
    }
    if (lane == 0) {
        int i0 = 0;
#pragma unroll
        for (int e = 1; e < EE; e++) if (logit[e] > logit[i0]) i0 = e;
        int i1 = (i0 == 0) ? 1 : 0;
#pragma unroll
        for (int e = 0; e < EE; e++) {
            if (e == i0) continue;
            if (logit[e] > logit[i1]) i1 = e;
        }
        float d = logit[i1] - logit[i0];
        float z = expf(d);
        float w0 = 1.0f / (1.0f + z);
        g_topk_idx[warp][0] = i0;
        g_topk_idx[warp][1] = i1;
        g_topk_w[warp][0] = w0;
        g_topk_w[warp][1] = z * w0;
    }
}
__global__ void build_kernel() {
    __shared__ int s_cnt[EE];
    __shared__ int s_cur[EE];
    int tid = threadIdx.x;
    if (tid < EE) s_cnt[tid] = 0;
    __syncthreads();
    for (int p = tid; p < NPAIR; p += blockDim.x)
        atomicAdd(&s_cnt[g_topk_idx[p >> 1][p & 1]], 1);
    __syncthreads();
    if (tid == 0) {
        int off = 0;
        for (int e = 0; e < EE; e++) {
            g_offsets[e] = off;
            g_counts[e]  = s_cnt[e];
            s_cur[e]     = off;
            off += s_cnt[e];
        }
    }
    __syncthreads();
    for (int p = tid; p < NPAIR; p += blockDim.x) {
        int t = p >> 1, k = p & 1;
        int e = g_topk_idx[t][k];
        int slot = atomicAdd(&s_cur[e], 1);
        g_pair_token[slot] = t;
        g_pair_w[slot]     = g_topk_w[t][k];
    }
}

// ======================= GEMM1: act = silu(x@w1^T) * (x@w3^T) =======================
// CTA 128 rows x 64 f-cols; warps 0-3 g (w1 rows 0-63 of B tile), warps 4-7 u (w3, rows 64-127).
// 3-stage cp.async pipeline, fp32 staging, tf32 single-pass mma.
__global__ __launch_bounds__(256)
void gemm1_kernel(const float* __restrict__ x,
                  const float* __restrict__ w1, const float* __restrict__ w3) {
    extern __shared__ float dsm[];
    __shared__ int s_tok[128];

    int e    = blockIdx.z;
    int n_e  = g_counts[e];
    int row0 = blockIdx.y * 128;
    if (row0 >= n_e) return;
    int f0   = blockIdx.x * 64;
    int base = g_offsets[e];
    int tid  = threadIdx.x;

    if (tid < 128) {
        int r = row0 + tid;
        s_tok[tid] = (r < n_e) ? g_pair_token[base + r] : 0;
    }
    __syncthreads();

    // cp.async descriptors: 4 A 16B-chunks + 4 B 16B-chunks per thread per k-chunk
    const char* srcA[4];
    const char* srcB[4];
    int dofA[4], dofB[4];
#pragma unroll
    for (int i = 0; i < 4; i++) {
        int idx = tid + 256 * i;
        int row = idx >> 3, c = idx & 7;
        srcA[i] = (const char*)(x + (size_t)s_tok[row] * HH) + c * 16;
        const float* wb = (row < 64)
            ? w1 + ((size_t)e * FF + f0 + row) * HH
            : w3 + ((size_t)e * FF + f0 + row - 64) * HH;
        srcB[i] = (const char*)wb + c * 16;
        dofA[i] = row * ROWB + c * 16;
        dofB[i] = ASTG + row * ROWB + c * 16;
    }
    uint32_t sb0 = smem_u32(dsm);
    auto issue = [&](int s) {
        uint32_t sg = sb0 + s * STG;
#pragma unroll
        for (int i = 0; i < 4; i++) { CP16(sg + dofA[i], srcA[i]); srcA[i] += 128; }
#pragma unroll
        for (int i = 0; i < 4; i++) { CP16(sg + dofB[i], srcB[i]); srcB[i] += 128; }
        CP_COMMIT();
    };
    issue(0);
    issue(1);

    int wid = tid >> 5, lane = tid & 31;
    int isU = wid >> 2;
    int rowblk = (wid & 3) * 32;
    int r4 = lane >> 2, qk = lane & 3;

    float acc[2][8][4];
#pragma unroll
    for (int mt = 0; mt < 2; mt++)
#pragma unroll
        for (int nt = 0; nt < 8; nt++)
#pragma unroll
            for (int i = 0; i < 4; i++) acc[mt][nt][i] = 0.0f;

    const int NC = HH / BK;   // 32
    for (int c = 0; c < NC; c++) {
        if (c < NC - 1) { CP_WAIT(1); } else { CP_WAIT(0); }
        __syncthreads();
        if (c + 2 < NC) issue((c + 2) % NS);

        const float* stg = dsm + (size_t)(c % NS) * (STG / 4);
        const float* sA = stg;
        const float* sB = stg + ASTG / 4 + (isU * 64) * ROWF;
#pragma unroll
        for (int ko = 0; ko < 4; ko++) {
            int kb = ko * 8 + qk;
            unsigned af[2][4];
#pragma unroll
            for (int mt = 0; mt < 2; mt++) {
                const float* p = sA + (rowblk + mt * 16 + r4) * ROWF + kb;
                af[mt][0] = tf32r(p[0]);
                af[mt][1] = tf32r(p[8 * ROWF]);
                af[mt][2] = tf32r(p[4]);
                af[mt][3] = tf32r(p[8 * ROWF + 4]);
            }
#pragma unroll
            for (int nt = 0; nt < 8; nt++) {
                const float* q = sB + (nt * 8 + r4) * ROWF + kb;
                unsigned b0 = tf32r(q[0]);
                unsigned b1 = tf32r(q[4]);
                mma1688(acc[0][nt], af[0], b0, b1);
                mma1688(acc[1][nt], af[1], b0, b1);
            }
        }
    }
    __syncthreads();   // mma reads done before smem reuse

    // ---- epilogue: u-warps publish via smem; g-warps combine; coalesced store ----
    float* epf = dsm;   // 128 x 64, stride 66
    if (isU) {
#pragma unroll
        for (int mt = 0; mt < 2; mt++)
#pragma unroll
            for (int nt = 0; nt < 8; nt++)
#pragma unroll
                for (int i = 0; i < 4; i++) {
                    int row = rowblk + mt * 16 + r4 + ((i >> 1) ? 8 : 0);
                    int col = nt * 8 + qk * 2 + (i & 1);
                    epf[row * 66 + col] = acc[mt][nt][i];
                }
    }
    __syncthreads();
    if (!isU) {
#pragma unroll
        for (int mt = 0; mt < 2; mt++)
#pragma unroll
            for (int nt = 0; nt < 8; nt++)
#pragma unroll
                for (int i = 0; i < 4; i++) {
                    int row = rowblk + mt * 16 + r4 + ((i >> 1) ? 8 : 0);
                    int col = nt * 8 + qk * 2 + (i & 1);
                    float u = epf[row * 66 + col];
                    float g = acc[mt][nt][i];
                    epf[row * 66 + col] = (g / (1.0f + expf(-g))) * u;
                }
    }
    __syncthreads();
    for (int idx = tid; idx < 128 * 64; idx += 256) {
        int rr = idx >> 6, cc = idx & 63;
        if (row0 + rr < n_e)
            g_act[(size_t)(base + row0 + rr) * FF + f0 + cc] = epf[rr * 66 + cc];
    }
}

// ======================= GEMM2: out += wt * (act @ w2^T) =======================
// CTA 128 rows x 128 h-cols; warps 4x2 (32x64 per warp).
__global__ __launch_bounds__(256)
void gemm2_kernel(const float* __restrict__ w2, float* __restrict__ out) {
    extern __shared__ float dsm[];
    __shared__ int   s_tok[128];
    __shared__ float s_wt[128];

    int e    = blockIdx.z;
    int n_e  = g_counts[e];
    int row0 = blockIdx.y * 128;
    if (row0 >= n_e) return;
    int h0   = blockIdx.x * 128;
    int base = g_offsets[e];
    int tid  = threadIdx.x;

    if (tid < 128) {
        int r = row0 + tid;
        s_tok[tid] = (r < n_e) ? g_pair_token[base + r] : 0;
        s_wt[tid]  = (r < n_e) ? g_pair_w[base + r] : 0.0f;
    }
    __syncthreads();

    const char* srcA[4];
    const char* srcB[4];
    int dofA[4], dofB[4];
#pragma unroll
    for (int i = 0; i < 4; i++) {
        int idx = tid + 256 * i;
        int row = idx >> 3, c = idx & 7;
        long arow = (long)base + row0 + row;
        if (arow > NPAIR - 1) arow = NPAIR - 1;
        srcA[i] = (const char*)(g_act + (size_t)arow * FF) + c * 16;
        srcB[i] = (const char*)(w2 + ((size_t)e * HH + h0 + row) * FF) + c * 16;
        dofA[i] = row * ROWB + c * 16;
        dofB[i] = ASTG + row * ROWB + c * 16;
    }
    uint32_t sb0 = smem_u32(dsm);
    auto issue = [&](int s) {
        uint32_t sg = sb0 + s * STG;
#pragma unroll
        for (int i = 0; i < 4; i++) { CP16(sg + dofA[i], srcA[i]); srcA[i] += 128; }
#pragma unroll
        for (int i = 0; i < 4; i++) { CP16(sg + dofB[i], srcB[i]); srcB[i] += 128; }
        CP_COMMIT();
    };
    issue(0);
    issue(1);

    int wid = tid >> 5, lane = tid & 31;
    int rowblk = (wid & 3) * 32;
    int colblk = (wid >> 2) * 64;
    int r4 = lane >> 2, qk = lane & 3;

    float acc[2][8][4];
#pragma unroll
    for (int mt = 0; mt < 2; mt++)
#pragma unroll
        for (int nt = 0; nt < 8; nt++)
#pragma unroll
            for (int i = 0; i < 4; i++) acc[mt][nt][i] = 0.0f;

    const int NC = FF / BK;   // 112
    for (int c = 0; c < NC; c++) {
        if (c < NC - 1) { CP_WAIT(1); } else { CP_WAIT(0); }
        __syncthreads();
        if (c + 2 < NC) issue((c + 2) % NS);

        const float* stg = dsm + (size_t)(c % NS) * (STG / 4);
        const float* sA = stg;
        const float* sB = stg + ASTG / 4 + colblk * ROWF;
#pragma unroll
        for (int ko = 0; ko < 4; ko++) {
            int kb = ko * 8 + qk;
            unsigned af[2][4];
#pragma unroll
            for (int mt = 0; mt < 2; mt++) {
                const float* p = sA + (rowblk + mt * 16 + r4) * ROWF + kb;
                af[mt][0] = tf32r(p[0]);
                af[mt][1] = tf32r(p[8 * ROWF]);
                af[mt][2] = tf32r(p[4]);
                af[mt][3] = tf32r(p[8 * ROWF + 4]);
            }
#pragma unroll
            for (int nt = 0; nt < 8; nt++) {
                const float* q = sB + (nt * 8 + r4) * ROWF + kb;
                unsigned b0 = tf32r(q[0]);
                unsigned b1 = tf32r(q[4]);
                mma1688(acc[0][nt], af[0], b0, b1);
                mma1688(acc[1][nt], af[1], b0, b1);
            }
        }
    }

    // ---- epilogue: weighted atomic combine (exactly 2 adds per out element) ----
#pragma unroll
    for (int mt = 0; mt < 2; mt++)
#pragma unroll
        for (int i2 = 0; i2 < 2; i2++) {
            int row = rowblk + mt * 16 + r4 + i2 * 8;
            if (row0 + row >= n_e) continue;
            float wt = s_wt[row];
            float* op = out + (size_t)s_tok[row] * HH + h0;
#pragma unroll
            for (int nt = 0; nt < 8; nt++) {
                int col = colblk + nt * 8 + qk * 2;
                atomicAdd(op + col,     acc[mt][nt][i2 * 2]     * wt);
                atomicAdd(op + col + 1, acc[mt][nt][i2 * 2 + 1] * wt);
            }
        }
}

// ---------------- launch ----------------
extern "C" void kernel_launch(void* const* d_in, const int* in_sizes, int n_in,
                              void* d_out, int out_size) {
    (void)in_sizes; (void)n_in; (void)out_size;
    const float* x  = (const float*)d_in[0];
    const float* gw = (const float*)d_in[1];
    const float* w1 = (const float*)d_in[2];
    const float* w3 = (const float*)d_in[3];
    const float* w2 = (const float*)d_in[4];
    float* out = (float*)d_out;

    cudaFuncSetAttribute(gemm1_kernel, cudaFuncAttributeMaxDynamicSharedMemorySize, SMEM_DYN);
    cudaFuncSetAttribute(gemm2_kernel, cudaFuncAttributeMaxDynamicSharedMemorySize, SMEM_DYN);

    zero_kernel<<<(TT * HH + 255) / 256, 256>>>(out, TT * HH);
    router_kernel<<<TT / 8, 256>>>(x, gw);
    build_kernel<<<1, 256>>>();

    dim3 g1(FF / 64, TT / 128, EE);    // (56,16,8); dead tiles early-exit
    gemm1_kernel<<<g1, 256, SMEM_DYN>>>(x, w1, w3);

    dim3 g2(HH / 128, TT / 128, EE);   // (8,16,8)
    gemm2_kernel<<<g2, 256, SMEM_DYN>>>(w2, out);
}